// round 4
// baseline (speedup 1.0000x reference)
#include <cuda_runtime.h>
#include <math.h>

#define TT      441000
#define NBATCH  8
#define NB      3
#define TOUT    160000
#define FRAMES  1000
#define DTAP    36
#define LCH     512
#define WCH     448
#define NCHUNK  ((TT + LCH - 1) / LCH)   // 862

// ---------------- scratch (static device globals; no allocs) ----------------
__device__ float g_xT [TT * 8];    // transposed input  [n][batch]
__device__ float g_cos[TT * 4];    // heterodyne table  [n][band] (pad 4)
__device__ float g_xlp[TT * 32];   // cascade output    [n][seq]  (pad 32)
__device__ float g_tap[160 * DTAP];
__device__ int   g_i0 [160];

struct BQParams {
    float b0[4], b2[4], a1[4], a2[4];   // bandpass per band (b1 == 0)
    float lb0, lb1, lb2, la1, la2;      // lowpass (shared)
    float cosco[4];                     // f32(2*pi) * f32(center)
};

// ---------------- prep: transpose x + heterodyne cos table ----------------
// KEY (R3): XLA's algebraic simplifier rewrites x / const -> x * (1/const).
// So the reference's t is  fl32(n * fl32(1/44100)),  NOT an IEEE divide.
// The f32 argument a = fl32(coef * t) then matches the reference's bit
// pattern; cos of it is computed in f64 (exact Payne-Hanek), which agrees
// with libdevice __nv_cosf / libm cosf to <1e-7 on the same argument.
__global__ __launch_bounds__(256) void prep_kernel(const float* __restrict__ x, BQParams P) {
    int n = blockIdx.x * blockDim.x + threadIdx.x;
    if (n >= TT) return;
    const float RINV = 1.0f / 44100.0f;                  // fl32 reciprocal
    float t = __fmul_rn(__int2float_rn(n), RINV);        // XLA recip-multiply

    float4 a, b;
    a.x = x[0 * TT + n]; a.y = x[1 * TT + n]; a.z = x[2 * TT + n]; a.w = x[3 * TT + n];
    b.x = x[4 * TT + n]; b.y = x[5 * TT + n]; b.z = x[6 * TT + n]; b.w = x[7 * TT + n];
    *reinterpret_cast<float4*>(&g_xT[n * 8])     = a;
    *reinterpret_cast<float4*>(&g_xT[n * 8 + 4]) = b;

    float4 c;
    c.x = (float)cos((double)__fmul_rn(P.cosco[0], t));
    c.y = (float)cos((double)__fmul_rn(P.cosco[1], t));
    c.z = (float)cos((double)__fmul_rn(P.cosco[2], t));
    c.w = 0.0f;
    *reinterpret_cast<float4*>(&g_cos[n * 4]) = c;
}

// ---------------- compact polyphase sinc taps (torchaudio formula, f64) ----------------
__global__ void taps_kernel() {
    int p = threadIdx.x;              // 0..159
    if (p >= 160) return;
    const double PI_D  = 3.14159265358979323846264338328;
    const double base  = 160.0 * 0.99;        // min(orig,new)*rolloff
    const double scale = base / 441.0;

    // first i (0..474) with pre-clip t*base > -6 (strictly): monotone in i
    int i0 = 0;
    for (int i = 0; i < 475; i++) {
        double tr = (-(double)p / 160.0 + ((double)i - 17.0) / 441.0) * base;
        if (tr > -6.0) { i0 = i; break; }
    }
    g_i0[p] = i0;

    for (int d = 0; d < DTAP; d++) {
        int i = i0 + d;
        float v = 0.0f;
        if (i < 475) {
            double tq = -(double)p / 160.0 + ((double)i - 17.0) / 441.0;
            double tc = tq * base;
            if (tc < -6.0) tc = -6.0;
            if (tc >  6.0) tc =  6.0;
            double w  = cos(tc * PI_D / 6.0 / 2.0);
            w = w * w;
            double tp_ = tc * PI_D;
            double s = (tp_ == 0.0) ? 1.0 : sin(tp_) / tp_;
            v = (float)(s * w * scale);
        }
        g_tap[p * DTAP + d] = v;
    }
}

// ---------------- cascade: bandpass -> clip -> mix -> lowpass -> clip ----------------
// One warp per time-chunk; lane = sequence (band*8+batch), 24 active.
// Warm-up of WCH samples makes chunks independent (worst pole radius 0.9357 -> 1e-13).
__global__ __launch_bounds__(128) void biquad_kernel(BQParams P) {
    int w    = (blockIdx.x * blockDim.x + threadIdx.x) >> 5;
    int lane = threadIdx.x & 31;
    if (w >= NCHUNK) return;

    int band  = (lane < 24) ? (lane >> 3) : 0;
    int batch = lane & 7;
    float b0 = P.b0[band], b2 = P.b2[band], a1 = P.a1[band], a2 = P.a2[band];
    float lb0 = P.lb0, lb1 = P.lb1, lb2 = P.lb2, la1 = P.la1, la2 = P.la2;

    int nstart = w * LCH;
    int nend   = min(nstart + LCH, TT);
    int n0     = max(nstart - WCH, 0);

    float x1 = 0.f, x2 = 0.f, y1 = 0.f, y2 = 0.f;
    float u1 = 0.f, u2 = 0.f, v1 = 0.f, v2 = 0.f;

    // warm-up (no stores)
    #pragma unroll 4
    for (int n = n0; n < nstart; ++n) {
        float xv = g_xT[n * 8 + batch];
        float cv = g_cos[n * 4 + band];
        float y  = b0 * xv + b2 * x2 - a1 * y1 - a2 * y2;
        x2 = x1; x1 = xv; y2 = y1; y1 = y;
        float yc  = fminf(1.0f, fmaxf(-1.0f, y));
        float mix = yc * cv;
        float v   = lb0 * mix + lb1 * u1 + lb2 * u2 - la1 * v1 - la2 * v2;
        u2 = u1; u1 = mix; v2 = v1; v1 = v;
    }
    // output region
    #pragma unroll 4
    for (int n = nstart; n < nend; ++n) {
        float xv = g_xT[n * 8 + batch];
        float cv = g_cos[n * 4 + band];
        float y  = b0 * xv + b2 * x2 - a1 * y1 - a2 * y2;
        x2 = x1; x1 = xv; y2 = y1; y1 = y;
        float yc  = fminf(1.0f, fmaxf(-1.0f, y));
        float mix = yc * cv;
        float v   = lb0 * mix + lb1 * u1 + lb2 * u2 - la1 * v1 - la2 * v2;
        u2 = u1; u1 = mix; v2 = v1; v1 = v;
        g_xlp[n * 32 + lane] = fminf(1.0f, fmaxf(-1.0f, v));
    }
}

// ---------------- polyphase resample 44100 -> 16000, compact 36-tap kernel ----------------
// Block = one output frame m (160 outputs x 24 sequences). Window staged in smem
// (row pad 25 breaks stride-32 bank conflicts). Taps live in registers (p fixed/thread).
__global__ __launch_bounds__(480) void resample_kernel(float* __restrict__ out) {
    __shared__ float win[474 * 25];            // 47.4 KB
    int m   = blockIdx.x;
    int tid = threadIdx.x;
    int nbase = 441 * m - 16;                  // row r <-> input sample n = nbase + r (j = r+1)

    for (int idx = tid; idx < 474 * 32; idx += 480) {
        int r = idx >> 5, c = idx & 31;
        int n = nbase + r;
        float v = (n >= 0 && n < TT && c < 24) ? g_xlp[n * 32 + c] : 0.0f;
        if (c < 24) win[r * 25 + c] = v;
    }

    int p  = tid % 160;
    int sg = tid / 160;                        // band group 0..2
    int i0 = g_i0[p];
    float tp[DTAP];
    #pragma unroll
    for (int d = 0; d < DTAP; d++) tp[d] = g_tap[p * DTAP + d];
    __syncthreads();

    const float* wb = &win[(i0 - 1) * 25 + sg * 8];
    float acc[8];
    #pragma unroll
    for (int k = 0; k < 8; k++) acc[k] = 0.0f;
    #pragma unroll
    for (int d = 0; d < DTAP; d++) {
        float tv = tp[d];
        #pragma unroll
        for (int k = 0; k < 8; k++)
            acc[k] = __fmaf_rn(tv, wb[d * 25 + k], acc[k]);
    }
    #pragma unroll
    for (int k = 0; k < 8; k++) {
        // seq = sg*8+k -> band = sg, batch = k ; out layout (batch, band, TOUT)
        out[(k * NB + sg) * TOUT + m * 160 + p] = acc[k];
    }
}

// ---------------- host ----------------
extern "C" void kernel_launch(void* const* d_in, const int* in_sizes, int n_in,
                              void* d_out, int out_size) {
    (void)in_sizes; (void)n_in; (void)out_size;
    const float* x = (const float*)d_in[0];
    float* out = (float*)d_out;

    const double PI_D = 3.14159265358979323846264338328;
    BQParams P;
    double centers[3] = {4000.0, 12000.0, 19025.0};
    double bws[3]     = {8000.0, 8000.0, 6050.0};
    for (int bnd = 0; bnd < 3; bnd++) {
        double c = centers[bnd];
        double Q = c / bws[bnd]; if (Q < 0.5) Q = 0.5;
        double w0 = 2.0 * PI_D * c / 44100.0;
        double alpha = sin(w0) / (2.0 * Q);
        double a0 = 1.0 + alpha;
        P.b0[bnd] = (float)(alpha / a0);
        P.b2[bnd] = (float)(-alpha / a0);
        P.a1[bnd] = (float)(-2.0 * cos(w0) / a0);
        P.a2[bnd] = (float)((1.0 - alpha) / a0);
        P.cosco[bnd] = (float)(2.0 * PI_D) * (float)c;   // f32(2pi) * f32(center), f32 mult
    }
    P.b0[3] = P.b2[3] = P.a1[3] = P.a2[3] = 0.0f;
    P.cosco[3] = 0.0f;
    {
        double cutoff = 0.45 * 16000.0;
        double Qc = 0.7071067811865476;
        double w0 = 2.0 * PI_D * cutoff / 44100.0;
        double alpha = sin(w0) / (2.0 * Qc);
        double cc = cos(w0);
        double a0 = 1.0 + alpha;
        P.lb0 = (float)((1.0 - cc) / 2.0 / a0);
        P.lb1 = (float)((1.0 - cc) / a0);
        P.lb2 = (float)((1.0 - cc) / 2.0 / a0);
        P.la1 = (float)(-2.0 * cc / a0);
        P.la2 = (float)((1.0 - alpha) / a0);
    }

    prep_kernel<<<(TT + 255) / 256, 256>>>(x, P);
    taps_kernel<<<1, 160>>>();
    biquad_kernel<<<(NCHUNK + 3) / 4, 128>>>(P);
    resample_kernel<<<FRAMES, 480>>>(out);
}

// round 5
// speedup vs baseline: 4.0527x; 4.0527x over previous
#include <cuda_runtime.h>
#include <math.h>

#define TT      441000
#define NB      3
#define TOUT    160000
#define FRAMES  1000
#define DTAP    36
#define LCH     512
#define WCH     288
#define NCHUNK  ((TT + LCH - 1) / LCH)   // 862

// ---------------- scratch (static device globals; no allocs) ----------------
__device__ float g_cos[TT * 4];    // heterodyne table  [n][band] (pad 4)
__device__ float g_xlp[TT * 24];   // cascade output    [n][seq]
__device__ float g_tap[DTAP * 160];// taps, transposed  [d][p]
__device__ int   g_i0 [160];

struct BQParams {
    float b0[4], b2[4], a1[4], a2[4];   // bandpass per band (b1 == 0)
    float lb0, lb1, lb2, la1, la2;      // lowpass (shared)
    float cosco[4];                     // f32(2*pi) * f32(center)
};

// cos of large f32 arg: 2-term Cody-Waite (FMA-exact, err ~2.5e-7 rad) + __cosf.
// Evaluation path proven interchangeable with f64 cos in R1/R2 (bit-identical rel_err).
__device__ __forceinline__ float cos_big(float a) {
    const double TWO_PI_D = 6.283185307179586476925287;
    const float  P1 = (float)TWO_PI_D;
    const float  P2 = (float)(TWO_PI_D - (double)((float)TWO_PI_D));
    const float  INV2PI = (float)(1.0 / TWO_PI_D);
    float k = rintf(__fmul_rn(a, INV2PI));
    float r = __fmaf_rn(-k, P1, a);
    r = __fmaf_rn(-k, P2, r);
    return __cosf(r);
}

// ---------------- prep: heterodyne cos table only ----------------
// t = fl32(n * fl32(1/44100))  (XLA recip-multiply, verified R4)
__global__ __launch_bounds__(256) void prep_kernel(BQParams P) {
    int n = blockIdx.x * blockDim.x + threadIdx.x;
    if (n >= TT) return;
    const float RINV = 1.0f / 44100.0f;
    float t = __fmul_rn(__int2float_rn(n), RINV);
    float4 c;
    c.x = cos_big(__fmul_rn(P.cosco[0], t));
    c.y = cos_big(__fmul_rn(P.cosco[1], t));
    c.z = cos_big(__fmul_rn(P.cosco[2], t));
    c.w = 0.0f;
    *reinterpret_cast<float4*>(&g_cos[n * 4]) = c;
}

// ---------------- polyphase sinc taps, parallel: block=d, thread=p ----------------
__device__ __forceinline__ double tap_tr(int p, int i) {
    const double base = 160.0 * 0.99;
    return (-(double)p / 160.0 + ((double)i - 17.0) / 441.0) * base;  // exact original expr
}

__global__ void taps_kernel() {
    int p = threadIdx.x;              // 0..159
    int d = blockIdx.x;               // 0..35
    const double PI_D  = 3.14159265358979323846264338328;
    const double base  = 160.0 * 0.99;
    const double scale = base / 441.0;

    // i0 = min i with tr(i) > -6 : closed-form guess + authoritative fixup
    double lim = 17.0 + 441.0 * ((double)p / 160.0 - 6.0 / base);
    int i0 = (int)ceil(lim);
    if (i0 < 0) i0 = 0;
    while (!(tap_tr(p, i0) > -6.0)) i0++;
    while (i0 > 0 && tap_tr(p, i0 - 1) > -6.0) i0--;
    if (d == 0) g_i0[p] = i0;

    int i = i0 + d;
    float v = 0.0f;
    if (i < 475) {
        double tq = -(double)p / 160.0 + ((double)i - 17.0) / 441.0;
        double tc = tq * base;
        if (tc < -6.0) tc = -6.0;
        if (tc >  6.0) tc =  6.0;
        double w  = cos(tc * PI_D / 6.0 / 2.0);
        w = w * w;
        double tp_ = tc * PI_D;
        double s = (tp_ == 0.0) ? 1.0 : sin(tp_) / tp_;
        v = (float)(s * w * scale);
    }
    g_tap[d * 160 + p] = v;
}

// ---------------- cascade: bandpass -> clip -> mix -> lowpass -> clip ----------------
// One warp per time-chunk; lane = sequence (band*8+batch), 24 active.
// Warm-up WCH=288: worst pole 0.9354 -> residual 4.6e-9.
__global__ __launch_bounds__(128) void biquad_kernel(const float* __restrict__ x, BQParams P) {
    int w    = (blockIdx.x * blockDim.x + threadIdx.x) >> 5;
    int lane = threadIdx.x & 31;
    if (w >= NCHUNK) return;

    int band  = (lane < 24) ? (lane >> 3) : 0;
    int batch = lane & 7;
    float b0 = P.b0[band], b2 = P.b2[band], a1 = P.a1[band], a2 = P.a2[band];
    float lb0 = P.lb0, lb1 = P.lb1, lb2 = P.lb2, la1 = P.la1, la2 = P.la2;

    int nstart = w * LCH;
    int nend   = min(nstart + LCH, TT);
    int n0     = max(nstart - WCH, 0);
    const float* xr = x + batch * TT;

    float x1 = 0.f, x2 = 0.f, y1 = 0.f, y2 = 0.f;
    float u1 = 0.f, u2 = 0.f, v1 = 0.f, v2 = 0.f;

    #pragma unroll 4
    for (int n = n0; n < nstart; ++n) {
        float xv = xr[n];
        float cv = g_cos[n * 4 + band];
        float y  = b0 * xv + b2 * x2 - a1 * y1 - a2 * y2;
        x2 = x1; x1 = xv; y2 = y1; y1 = y;
        float yc  = fminf(1.0f, fmaxf(-1.0f, y));
        float mix = yc * cv;
        float v   = lb0 * mix + lb1 * u1 + lb2 * u2 - la1 * v1 - la2 * v2;
        u2 = u1; u1 = mix; v2 = v1; v1 = v;
    }
    #pragma unroll 4
    for (int n = nstart; n < nend; ++n) {
        float xv = xr[n];
        float cv = g_cos[n * 4 + band];
        float y  = b0 * xv + b2 * x2 - a1 * y1 - a2 * y2;
        x2 = x1; x1 = xv; y2 = y1; y1 = y;
        float yc  = fminf(1.0f, fmaxf(-1.0f, y));
        float mix = yc * cv;
        float v   = lb0 * mix + lb1 * u1 + lb2 * u2 - la1 * v1 - la2 * v2;
        u2 = u1; u1 = mix; v2 = v1; v1 = v;
        if (lane < 24) g_xlp[n * 24 + lane] = fminf(1.0f, fmaxf(-1.0f, v));
    }
}

// ---------------- polyphase resample 44100 -> 16000 ----------------
// Block = (frame m, band-group sg). 160 threads = phases p. smem window
// 474 rows x 8 seqs, pitch 9 (odd -> conflict-free). Taps in registers.
__global__ __launch_bounds__(160, 6) void resample_kernel(float* __restrict__ out) {
    __shared__ float win[474 * 9];             // 17 KB
    int m   = blockIdx.x;
    int sg  = blockIdx.y;                      // 0..2
    int tid = threadIdx.x;                     // = p
    int nbase = 441 * m - 16;                  // row r <-> input sample n = nbase + r

    // stage: 474 rows x 2 float4 = 948 tasks
    for (int idx = tid; idx < 948; idx += 160) {
        int r = idx >> 1, half = idx & 1;
        int n = nbase + r;
        float4 v = make_float4(0.f, 0.f, 0.f, 0.f);
        if (n >= 0 && n < TT)
            v = *reinterpret_cast<const float4*>(&g_xlp[n * 24 + sg * 8 + half * 4]);
        float* wv = &win[r * 9 + half * 4];
        wv[0] = v.x; wv[1] = v.y; wv[2] = v.z; wv[3] = v.w;
    }

    int p  = tid;
    int i0 = g_i0[p];
    float tp[DTAP];
    #pragma unroll
    for (int d = 0; d < DTAP; d++) tp[d] = g_tap[d * 160 + p];   // coalesced
    __syncthreads();

    const float* wb = &win[(i0 - 1) * 9];
    float acc[8];
    #pragma unroll
    for (int k = 0; k < 8; k++) acc[k] = 0.0f;
    #pragma unroll
    for (int d = 0; d < DTAP; d++) {
        float tv = tp[d];
        #pragma unroll
        for (int k = 0; k < 8; k++)
            acc[k] = __fmaf_rn(tv, wb[d * 9 + k], acc[k]);
    }
    #pragma unroll
    for (int k = 0; k < 8; k++) {
        // seq = sg*8+k -> band = sg, batch = k ; out layout (batch, band, TOUT)
        out[(k * NB + sg) * TOUT + m * 160 + p] = acc[k];
    }
}

// ---------------- host ----------------
extern "C" void kernel_launch(void* const* d_in, const int* in_sizes, int n_in,
                              void* d_out, int out_size) {
    (void)in_sizes; (void)n_in; (void)out_size;
    const float* x = (const float*)d_in[0];
    float* out = (float*)d_out;

    const double PI_D = 3.14159265358979323846264338328;
    BQParams P;
    double centers[3] = {4000.0, 12000.0, 19025.0};
    double bws[3]     = {8000.0, 8000.0, 6050.0};
    for (int bnd = 0; bnd < 3; bnd++) {
        double c = centers[bnd];
        double Q = c / bws[bnd]; if (Q < 0.5) Q = 0.5;
        double w0 = 2.0 * PI_D * c / 44100.0;
        double alpha = sin(w0) / (2.0 * Q);
        double a0 = 1.0 + alpha;
        P.b0[bnd] = (float)(alpha / a0);
        P.b2[bnd] = (float)(-alpha / a0);
        P.a1[bnd] = (float)(-2.0 * cos(w0) / a0);
        P.a2[bnd] = (float)((1.0 - alpha) / a0);
        P.cosco[bnd] = (float)(2.0 * PI_D) * (float)c;   // f32(2pi) * f32(center)
    }
    P.b0[3] = P.b2[3] = P.a1[3] = P.a2[3] = 0.0f;
    P.cosco[3] = 0.0f;
    {
        double cutoff = 0.45 * 16000.0;
        double Qc = 0.7071067811865476;
        double w0 = 2.0 * PI_D * cutoff / 44100.0;
        double alpha = sin(w0) / (2.0 * Qc);
        double cc = cos(w0);
        double a0 = 1.0 + alpha;
        P.lb0 = (float)((1.0 - cc) / 2.0 / a0);
        P.lb1 = (float)((1.0 - cc) / a0);
        P.lb2 = (float)((1.0 - cc) / 2.0 / a0);
        P.la1 = (float)(-2.0 * cc / a0);
        P.la2 = (float)((1.0 - alpha) / a0);
    }

    taps_kernel<<<DTAP, 160>>>();
    prep_kernel<<<(TT + 255) / 256, 256>>>(P);
    biquad_kernel<<<(NCHUNK * 32 + 127) / 128, 128>>>(x, P);
    dim3 rg(FRAMES, NB);
    resample_kernel<<<rg, 160>>>(out);
}

// round 6
// speedup vs baseline: 7.5658x; 1.8669x over previous
#include <cuda_runtime.h>
#include <math.h>

#define TT      441000
#define NB      3
#define TOUT    160000
#define FRAMES  1000
#define DTAP    36
#define LCH     256
#define WCH     192
#define NCHUNK  ((TT + LCH - 1) / LCH)   // 1723

// ---------------- scratch (static device globals; no allocs) ----------------
__device__ float g_cosP[NB * TT];     // heterodyne table, planar [band][n]
__device__ float g_xlp [TT * 24];     // cascade output [n][seq]
__device__ float g_tapP[160 * DTAP];  // taps [p][d]  (float4-friendly per p)
__device__ int   g_i0  [160];

struct BQParams {
    float b0[4], b2[4], a1[4], a2[4];
    float lb0, lb1, lb2, la1, la2;
    float cosco[4];                   // f32(2*pi) * f32(center)
};

// cos of large f32 arg: 2-term Cody-Waite (FMA-exact) + __cosf (validated R1/R2/R5).
__device__ __forceinline__ float cos_big(float a) {
    const double TWO_PI_D = 6.283185307179586476925287;
    const float  P1 = (float)TWO_PI_D;
    const float  P2 = (float)(TWO_PI_D - (double)((float)TWO_PI_D));
    const float  INV2PI = (float)(1.0 / TWO_PI_D);
    float k = rintf(__fmul_rn(a, INV2PI));
    float r = __fmaf_rn(-k, P1, a);
    r = __fmaf_rn(-k, P2, r);
    return __cosf(r);
}

// ---------------- prep: heterodyne cos table, planar ----------------
// t = fl32(n * fl32(1/44100))  (XLA recip-multiply, verified R4)
__global__ __launch_bounds__(256) void prep_kernel(BQParams P) {
    int n = blockIdx.x * blockDim.x + threadIdx.x;
    if (n >= TT) return;
    const float RINV = 1.0f / 44100.0f;
    float t = __fmul_rn(__int2float_rn(n), RINV);
    g_cosP[0 * TT + n] = cos_big(__fmul_rn(P.cosco[0], t));
    g_cosP[1 * TT + n] = cos_big(__fmul_rn(P.cosco[1], t));
    g_cosP[2 * TT + n] = cos_big(__fmul_rn(P.cosco[2], t));
}

// ---------------- polyphase sinc taps, parallel: block=d, thread=p ----------------
__device__ __forceinline__ double tap_tr(int p, int i) {
    const double base = 160.0 * 0.99;
    return (-(double)p / 160.0 + ((double)i - 17.0) / 441.0) * base;
}

__global__ void taps_kernel() {
    int p = threadIdx.x;              // 0..159
    int d = blockIdx.x;               // 0..35
    const double PI_D  = 3.14159265358979323846264338328;
    const double base  = 160.0 * 0.99;
    const double scale = base / 441.0;

    double lim = 17.0 + 441.0 * ((double)p / 160.0 - 6.0 / base);
    int i0 = (int)ceil(lim);
    if (i0 < 0) i0 = 0;
    while (!(tap_tr(p, i0) > -6.0)) i0++;
    while (i0 > 0 && tap_tr(p, i0 - 1) > -6.0) i0--;
    if (d == 0) g_i0[p] = i0;

    int i = i0 + d;
    float v = 0.0f;
    if (i < 475) {
        double tq = -(double)p / 160.0 + ((double)i - 17.0) / 441.0;
        double tc = tq * base;
        if (tc < -6.0) tc = -6.0;
        if (tc >  6.0) tc =  6.0;
        double w  = cos(tc * PI_D / 6.0 / 2.0);
        w = w * w;
        double tp_ = tc * PI_D;
        double s = (tp_ == 0.0) ? 1.0 : sin(tp_) / tp_;
        v = (float)(s * w * scale);
    }
    g_tapP[p * DTAP + d] = v;
}

// ---------------- cascade: bandpass -> clip -> mix -> lowpass -> clip ----------------
// One warp per 256-sample chunk (1723 warps); lane = seq (band*8+batch), 24 active.
// Warm-up 192: worst pole 0.9357 -> leakage ~2.8e-6.
__global__ __launch_bounds__(128) void biquad_kernel(const float* __restrict__ x, BQParams P) {
    int w    = (blockIdx.x * blockDim.x + threadIdx.x) >> 5;
    int lane = threadIdx.x & 31;
    if (w >= NCHUNK) return;

    int band  = (lane < 24) ? (lane >> 3) : 0;
    int batch = lane & 7;
    float b0 = P.b0[band], b2 = P.b2[band], a1 = P.a1[band], a2 = P.a2[band];
    float lb0 = P.lb0, lb1 = P.lb1, lb2 = P.lb2, la1 = P.la1, la2 = P.la2;

    int nstart = w * LCH;
    int nend   = min(nstart + LCH, TT);          // always multiple of 4
    int n0     = max(nstart - WCH, 0);
    const float* xr = x + batch * TT;
    const float* cp = g_cosP + band * TT;

    float x1 = 0.f, x2 = 0.f, y1 = 0.f, y2 = 0.f;
    float u1 = 0.f, u2 = 0.f, v1 = 0.f, v2 = 0.f;

#define BQ_STEP(XV, CV, DO_STORE, NIDX)                                       \
    {                                                                          \
        float y  = b0 * (XV) + b2 * x2 - a1 * y1 - a2 * y2;                    \
        x2 = x1; x1 = (XV); y2 = y1; y1 = y;                                   \
        float yc  = fminf(1.0f, fmaxf(-1.0f, y));                              \
        float mix = yc * (CV);                                                 \
        float v   = lb0 * mix + lb1 * u1 + lb2 * u2 - la1 * v1 - la2 * v2;     \
        u2 = u1; u1 = mix; v2 = v1; v1 = v;                                    \
        if (DO_STORE && lane < 24)                                             \
            g_xlp[(NIDX) * 24 + lane] = fminf(1.0f, fmaxf(-1.0f, v));          \
    }

    #pragma unroll 2
    for (int n = n0; n < nstart; n += 4) {
        float4 xv = *reinterpret_cast<const float4*>(&xr[n]);
        float4 cv = *reinterpret_cast<const float4*>(&cp[n]);
        BQ_STEP(xv.x, cv.x, 0, n)
        BQ_STEP(xv.y, cv.y, 0, n)
        BQ_STEP(xv.z, cv.z, 0, n)
        BQ_STEP(xv.w, cv.w, 0, n)
    }
    #pragma unroll 2
    for (int n = nstart; n < nend; n += 4) {
        float4 xv = *reinterpret_cast<const float4*>(&xr[n]);
        float4 cv = *reinterpret_cast<const float4*>(&cp[n]);
        BQ_STEP(xv.x, cv.x, 1, n + 0)
        BQ_STEP(xv.y, cv.y, 1, n + 1)
        BQ_STEP(xv.z, cv.z, 1, n + 2)
        BQ_STEP(xv.w, cv.w, 1, n + 3)
    }
#undef BQ_STEP
}

// ---------------- polyphase resample 44100 -> 16000 ----------------
// Block = (frame m, band-group sg). 160 threads = phases. Window 474x8, pitch 9
// (conflict-spread). Taps streamed as float4 from gmem (L1-resident) -> low regs,
// 9 blocks/SM.
__global__ __launch_bounds__(160, 9) void resample_kernel(float* __restrict__ out) {
    __shared__ float win[474 * 9];             // 17 KB
    int m   = blockIdx.x;
    int sg  = blockIdx.y;                      // 0..2
    int tid = threadIdx.x;                     // = p
    int nbase = 441 * m - 16;                  // row r <-> input sample n = nbase + r

    for (int idx = tid; idx < 948; idx += 160) {
        int r = idx >> 1, half = idx & 1;
        int n = nbase + r;
        float4 v = make_float4(0.f, 0.f, 0.f, 0.f);
        if (n >= 0 && n < TT)
            v = *reinterpret_cast<const float4*>(&g_xlp[n * 24 + sg * 8 + half * 4]);
        float* wv = &win[r * 9 + half * 4];
        wv[0] = v.x; wv[1] = v.y; wv[2] = v.z; wv[3] = v.w;
    }

    int p  = tid;
    int i0 = g_i0[p];
    __syncthreads();

    const float* wb = &win[(i0 - 1) * 9];
    const float4* tq = reinterpret_cast<const float4*>(&g_tapP[p * DTAP]);
    float acc[8];
    #pragma unroll
    for (int k = 0; k < 8; k++) acc[k] = 0.0f;

    #pragma unroll
    for (int dq = 0; dq < DTAP / 4; dq++) {
        float4 t4 = __ldg(&tq[dq]);
        const float* w0 = wb + (dq * 4) * 9;
        #pragma unroll
        for (int k = 0; k < 8; k++) acc[k] = __fmaf_rn(t4.x, w0[k], acc[k]);
        #pragma unroll
        for (int k = 0; k < 8; k++) acc[k] = __fmaf_rn(t4.y, w0[9 + k], acc[k]);
        #pragma unroll
        for (int k = 0; k < 8; k++) acc[k] = __fmaf_rn(t4.z, w0[18 + k], acc[k]);
        #pragma unroll
        for (int k = 0; k < 8; k++) acc[k] = __fmaf_rn(t4.w, w0[27 + k], acc[k]);
    }
    #pragma unroll
    for (int k = 0; k < 8; k++) {
        // seq = sg*8+k -> band = sg, batch = k ; out layout (batch, band, TOUT)
        out[(k * NB + sg) * TOUT + m * 160 + p] = acc[k];
    }
}

// ---------------- host ----------------
extern "C" void kernel_launch(void* const* d_in, const int* in_sizes, int n_in,
                              void* d_out, int out_size) {
    (void)in_sizes; (void)n_in; (void)out_size;
    const float* x = (const float*)d_in[0];
    float* out = (float*)d_out;

    const double PI_D = 3.14159265358979323846264338328;
    BQParams P;
    double centers[3] = {4000.0, 12000.0, 19025.0};
    double bws[3]     = {8000.0, 8000.0, 6050.0};
    for (int bnd = 0; bnd < 3; bnd++) {
        double c = centers[bnd];
        double Q = c / bws[bnd]; if (Q < 0.5) Q = 0.5;
        double w0 = 2.0 * PI_D * c / 44100.0;
        double alpha = sin(w0) / (2.0 * Q);
        double a0 = 1.0 + alpha;
        P.b0[bnd] = (float)(alpha / a0);
        P.b2[bnd] = (float)(-alpha / a0);
        P.a1[bnd] = (float)(-2.0 * cos(w0) / a0);
        P.a2[bnd] = (float)((1.0 - alpha) / a0);
        P.cosco[bnd] = (float)(2.0 * PI_D) * (float)c;
    }
    P.b0[3] = P.b2[3] = P.a1[3] = P.a2[3] = 0.0f;
    P.cosco[3] = 0.0f;
    {
        double cutoff = 0.45 * 16000.0;
        double Qc = 0.7071067811865476;
        double w0 = 2.0 * PI_D * cutoff / 44100.0;
        double alpha = sin(w0) / (2.0 * Qc);
        double cc = cos(w0);
        double a0 = 1.0 + alpha;
        P.lb0 = (float)((1.0 - cc) / 2.0 / a0);
        P.lb1 = (float)((1.0 - cc) / a0);
        P.lb2 = (float)((1.0 - cc) / 2.0 / a0);
        P.la1 = (float)(-2.0 * cc / a0);
        P.la2 = (float)((1.0 - alpha) / a0);
    }

    taps_kernel<<<DTAP, 160>>>();
    prep_kernel<<<(TT + 255) / 256, 256>>>(P);
    biquad_kernel<<<(NCHUNK * 32 + 127) / 128, 128>>>(x, P);
    dim3 rg(FRAMES, NB);
    resample_kernel<<<rg, 160>>>(out);
}

// round 7
// speedup vs baseline: 9.2435x; 1.2217x over previous
#include <cuda_runtime.h>
#include <math.h>

#define TT      441000
#define NB      3
#define TOUT    160000
#define FRAMES  1000
#define DTAP    36
#define LCH     256
#define WCH     192
#define NCHUNK  ((TT + LCH - 1) / LCH)   // 1723
#define RSPAN   45                        // rows per 4-phase group (<= 9 + 36)
#define RTAB    48                        // padded row count in tap table
#define WPITCH  26                        // smem window pitch (floats)

// ---------------- scratch (static device globals; no allocs) ----------------
__device__ float g_cosP [NB * TT];        // heterodyne table, planar [band][n]
__device__ float g_xlp  [TT * 24];        // cascade output [n][seq]
__device__ float g_tapS4[RTAB * 160];     // shifted taps [r][p], p grouped by 4
__device__ int   g_i0q  [40];             // i0 of phase 4q

struct BQParams {
    float b0[4], b2[4], a1[4], a2[4];
    float lb0, lb1, lb2, la1, la2;
    float cosco[4];                       // f32(2*pi) * f32(center)
};

// FMA-only cos of large f32 arg: 2-term Cody-Waite to r in [-pi,pi], then
// cos(r) = 1 - 2*sin^2(r/2), sin via Taylor-9 on [-pi/2,pi/2]. Abs err ~5e-6,
// well inside budget (measured sensitivity: 0.07 rad err -> 1.26e-2 rel).
__device__ __forceinline__ float cos_poly(float a) {
    const double TWO_PI_D = 6.283185307179586476925287;
    const float  P1 = (float)TWO_PI_D;
    const float  P2 = (float)(TWO_PI_D - (double)((float)TWO_PI_D));
    const float  INV2PI = (float)(1.0 / TWO_PI_D);
    float k = rintf(__fmul_rn(a, INV2PI));
    float r = __fmaf_rn(-k, P1, a);
    r = __fmaf_rn(-k, P2, r);
    float h  = 0.5f * r;
    float h2 = h * h;
    const float c3 = -1.6666667e-1f, c5 = 8.3333333e-3f,
                c7 = -1.9841270e-4f, c9 = 2.7557319e-6f;
    float p = __fmaf_rn(c9, h2, c7);
    p = __fmaf_rn(p, h2, c5);
    p = __fmaf_rn(p, h2, c3);
    p = __fmaf_rn(p, h2, 1.0f);
    float s = p * h;
    return __fmaf_rn(-2.0f * s, s, 1.0f);
}

// ---------------- prep: heterodyne cos table, planar ----------------
// t = fl32(n * fl32(1/44100))  (XLA recip-multiply, verified R4)
__global__ __launch_bounds__(256) void prep_kernel(BQParams P) {
    int n = blockIdx.x * blockDim.x + threadIdx.x;
    if (n >= TT) return;
    const float RINV = 1.0f / 44100.0f;
    float t = __fmul_rn(__int2float_rn(n), RINV);
    g_cosP[0 * TT + n] = cos_poly(__fmul_rn(P.cosco[0], t));
    g_cosP[1 * TT + n] = cos_poly(__fmul_rn(P.cosco[1], t));
    g_cosP[2 * TT + n] = cos_poly(__fmul_rn(P.cosco[2], t));
}

// ---------------- shifted/transposed polyphase taps ----------------
__device__ __forceinline__ double tap_tr(int p, int i) {
    const double base = 160.0 * 0.99;
    return (-(double)p / 160.0 + ((double)i - 17.0) / 441.0) * base;
}
__device__ __forceinline__ int tap_i0(int p) {
    const double base = 160.0 * 0.99;
    double lim = 17.0 + 441.0 * ((double)p / 160.0 - 6.0 / base);
    int i0 = (int)ceil(lim);
    if (i0 < 0) i0 = 0;
    while (!(tap_tr(p, i0) > -6.0)) i0++;
    while (i0 > 0 && tap_tr(p, i0 - 1) > -6.0) i0--;
    return i0;
}

// grid = RTAB blocks x 160 threads: thread (r, p)
__global__ void taps_kernel() {
    int p = threadIdx.x;              // 0..159
    int r = blockIdx.x;               // 0..RTAB-1
    const double PI_D  = 3.14159265358979323846264338328;
    const double base  = 160.0 * 0.99;
    const double scale = base / 441.0;

    int i0p  = tap_i0(p);
    int i0b  = tap_i0(p & ~3);        // group base
    if (r == 0 && (p & 3) == 0) g_i0q[p >> 2] = i0b;

    int i = i0b + r;                  // absolute kernel column
    int d = i - i0p;                  // tap index for this phase
    float v = 0.0f;
    if (d >= 0 && d < DTAP && i < 475) {
        double tq = -(double)p / 160.0 + ((double)i - 17.0) / 441.0;
        double tc = tq * base;
        if (tc < -6.0) tc = -6.0;
        if (tc >  6.0) tc =  6.0;
        double w  = cos(tc * PI_D / 6.0 / 2.0);
        w = w * w;
        double tp_ = tc * PI_D;
        double s = (tp_ == 0.0) ? 1.0 : sin(tp_) / tp_;
        v = (float)(s * w * scale);
    }
    g_tapS4[r * 160 + p] = v;
}

// ---------------- cascade: bandpass -> clip -> mix -> lowpass -> clip ----------------
__global__ __launch_bounds__(128) void biquad_kernel(const float* __restrict__ x, BQParams P) {
    int w    = (blockIdx.x * blockDim.x + threadIdx.x) >> 5;
    int lane = threadIdx.x & 31;
    if (w >= NCHUNK) return;

    int band  = (lane < 24) ? (lane >> 3) : 0;
    int batch = lane & 7;
    float b0 = P.b0[band], b2 = P.b2[band], a1 = P.a1[band], a2 = P.a2[band];
    float lb0 = P.lb0, lb1 = P.lb1, lb2 = P.lb2, la1 = P.la1, la2 = P.la2;

    int nstart = w * LCH;
    int nend   = min(nstart + LCH, TT);
    int n0     = max(nstart - WCH, 0);
    const float* xr = x + batch * TT;
    const float* cp = g_cosP + band * TT;

    float x1 = 0.f, x2 = 0.f, y1 = 0.f, y2 = 0.f;
    float u1 = 0.f, u2 = 0.f, v1 = 0.f, v2 = 0.f;

#define BQ_STEP(XV, CV, DO_STORE, NIDX)                                       \
    {                                                                          \
        float y  = b0 * (XV) + b2 * x2 - a1 * y1 - a2 * y2;                    \
        x2 = x1; x1 = (XV); y2 = y1; y1 = y;                                   \
        float yc  = fminf(1.0f, fmaxf(-1.0f, y));                              \
        float mix = yc * (CV);                                                 \
        float v   = lb0 * mix + lb1 * u1 + lb2 * u2 - la1 * v1 - la2 * v2;     \
        u2 = u1; u1 = mix; v2 = v1; v1 = v;                                    \
        if (DO_STORE && lane < 24)                                             \
            g_xlp[(NIDX) * 24 + lane] = fminf(1.0f, fmaxf(-1.0f, v));          \
    }

    #pragma unroll 2
    for (int n = n0; n < nstart; n += 4) {
        float4 xv = *reinterpret_cast<const float4*>(&xr[n]);
        float4 cv = *reinterpret_cast<const float4*>(&cp[n]);
        BQ_STEP(xv.x, cv.x, 0, n)
        BQ_STEP(xv.y, cv.y, 0, n)
        BQ_STEP(xv.z, cv.z, 0, n)
        BQ_STEP(xv.w, cv.w, 0, n)
    }
    #pragma unroll 2
    for (int n = nstart; n < nend; n += 4) {
        float4 xv = *reinterpret_cast<const float4*>(&xr[n]);
        float4 cv = *reinterpret_cast<const float4*>(&cp[n]);
        BQ_STEP(xv.x, cv.x, 1, n + 0)
        BQ_STEP(xv.y, cv.y, 1, n + 1)
        BQ_STEP(xv.z, cv.z, 1, n + 2)
        BQ_STEP(xv.w, cv.w, 1, n + 3)
    }
#undef BQ_STEP
}

// packed f32x2 fma: two independent rn FMAs (bit-identical to scalar)
__device__ __forceinline__ void fma2(float2& acc, unsigned long long tap2, const float2& w) {
    unsigned long long a = *reinterpret_cast<unsigned long long*>(&acc);
    unsigned long long wv = *reinterpret_cast<const unsigned long long*>(&w);
    asm("fma.rn.f32x2 %0, %1, %2, %0;" : "+l"(a) : "l"(tap2), "l"(wv));
    acc = *reinterpret_cast<float2*>(&a);
}
__device__ __forceinline__ unsigned long long pack2(float t) {
    unsigned long long r;
    asm("mov.b64 %0, {%1, %1};" : "=l"(r) : "r"(__float_as_uint(t)));
    return r;
}

// ---------------- polyphase resample 44100 -> 16000 ----------------
// Block = frame m. 120 threads = (sg 0..2) x (q 0..39); thread computes phases
// 4q..4q+3 for its 8 seqs: smem row reads are reused 4x in registers.
__global__ __launch_bounds__(128, 4) void resample_kernel(float* __restrict__ out) {
    __shared__ float win[475 * WPITCH];        // 49.4 KB
    int m   = blockIdx.x;
    int tid = threadIdx.x;
    int nbase = 441 * m - 16;                  // row r <-> input sample n = nbase + r

    // stage 475 rows x 24 floats as float2 (pitch 26 keeps 8B alignment)
    for (int idx = tid; idx < 475 * 12; idx += 128) {
        int r = idx / 12, c2 = idx % 12;
        int n = nbase + r;
        float2 v = make_float2(0.f, 0.f);
        if (n >= 0 && n < TT)
            v = *reinterpret_cast<const float2*>(&g_xlp[n * 24 + c2 * 2]);
        *reinterpret_cast<float2*>(&win[r * WPITCH + c2 * 2]) = v;
    }
    __syncthreads();

    if (tid >= 120) return;
    int sg = tid / 40;                         // 0..2
    int q  = tid % 40;                         // phase group
    int rb = g_i0q[q] - 1;                     // base window row

    float2 acc[4][4];                          // [phase j][k-pair]
    #pragma unroll
    for (int j = 0; j < 4; j++)
        #pragma unroll
        for (int k2 = 0; k2 < 4; k2++) acc[j][k2] = make_float2(0.f, 0.f);

    const float* wrow = &win[rb * WPITCH + sg * 8];
    const float4* tap = reinterpret_cast<const float4*>(&g_tapS4[4 * q]);

    #pragma unroll
    for (int r = 0; r < RSPAN; r++) {
        float4 t4 = __ldg(&tap[r * 40]);       // taps for 4 phases (coalesced)
        unsigned long long t0 = pack2(t4.x), t1 = pack2(t4.y),
                           t2 = pack2(t4.z), t3 = pack2(t4.w);
        const float* wr = wrow + r * WPITCH;
        float2 w0 = *reinterpret_cast<const float2*>(wr + 0);
        float2 w1 = *reinterpret_cast<const float2*>(wr + 2);
        float2 w2 = *reinterpret_cast<const float2*>(wr + 4);
        float2 w3 = *reinterpret_cast<const float2*>(wr + 6);
        fma2(acc[0][0], t0, w0); fma2(acc[0][1], t0, w1);
        fma2(acc[0][2], t0, w2); fma2(acc[0][3], t0, w3);
        fma2(acc[1][0], t1, w0); fma2(acc[1][1], t1, w1);
        fma2(acc[1][2], t1, w2); fma2(acc[1][3], t1, w3);
        fma2(acc[2][0], t2, w0); fma2(acc[2][1], t2, w1);
        fma2(acc[2][2], t2, w2); fma2(acc[2][3], t2, w3);
        fma2(acc[3][0], t3, w0); fma2(acc[3][1], t3, w1);
        fma2(acc[3][2], t3, w2); fma2(acc[3][3], t3, w3);
    }

    // out layout (batch k, band sg, TOUT); phases 4q+j contiguous -> float4 per k
    int obase = m * 160 + 4 * q;
    #pragma unroll
    for (int k = 0; k < 8; k++) {
        float4 o;
        o.x = (k & 1) ? acc[0][k >> 1].y : acc[0][k >> 1].x;
        o.y = (k & 1) ? acc[1][k >> 1].y : acc[1][k >> 1].x;
        o.z = (k & 1) ? acc[2][k >> 1].y : acc[2][k >> 1].x;
        o.w = (k & 1) ? acc[3][k >> 1].y : acc[3][k >> 1].x;
        *reinterpret_cast<float4*>(&out[(k * NB + sg) * TOUT + obase]) = o;
    }
}

// ---------------- host ----------------
extern "C" void kernel_launch(void* const* d_in, const int* in_sizes, int n_in,
                              void* d_out, int out_size) {
    (void)in_sizes; (void)n_in; (void)out_size;
    const float* x = (const float*)d_in[0];
    float* out = (float*)d_out;

    const double PI_D = 3.14159265358979323846264338328;
    BQParams P;
    double centers[3] = {4000.0, 12000.0, 19025.0};
    double bws[3]     = {8000.0, 8000.0, 6050.0};
    for (int bnd = 0; bnd < 3; bnd++) {
        double c = centers[bnd];
        double Q = c / bws[bnd]; if (Q < 0.5) Q = 0.5;
        double w0 = 2.0 * PI_D * c / 44100.0;
        double alpha = sin(w0) / (2.0 * Q);
        double a0 = 1.0 + alpha;
        P.b0[bnd] = (float)(alpha / a0);
        P.b2[bnd] = (float)(-alpha / a0);
        P.a1[bnd] = (float)(-2.0 * cos(w0) / a0);
        P.a2[bnd] = (float)((1.0 - alpha) / a0);
        P.cosco[bnd] = (float)(2.0 * PI_D) * (float)c;
    }
    P.b0[3] = P.b2[3] = P.a1[3] = P.a2[3] = 0.0f;
    P.cosco[3] = 0.0f;
    {
        double cutoff = 0.45 * 16000.0;
        double Qc = 0.7071067811865476;
        double w0 = 2.0 * PI_D * cutoff / 44100.0;
        double alpha = sin(w0) / (2.0 * Qc);
        double cc = cos(w0);
        double a0 = 1.0 + alpha;
        P.lb0 = (float)((1.0 - cc) / 2.0 / a0);
        P.lb1 = (float)((1.0 - cc) / a0);
        P.lb2 = (float)((1.0 - cc) / 2.0 / a0);
        P.la1 = (float)(-2.0 * cc / a0);
        P.la2 = (float)((1.0 - alpha) / a0);
    }

    taps_kernel<<<RTAB, 160>>>();
    prep_kernel<<<(TT + 255) / 256, 256>>>(P);
    biquad_kernel<<<(NCHUNK * 32 + 127) / 128, 128>>>(x, P);
    resample_kernel<<<FRAMES, 128>>>(out);
}

// round 8
// speedup vs baseline: 9.7799x; 1.0580x over previous
#include <cuda_runtime.h>
#include <math.h>

#define TT      441000
#define NB      3
#define TOUT    160000
#define FRAMES  1000
#define DTAP    36
#define LCH     256
#define WCH     128
#define NCHUNK  ((TT + LCH - 1) / LCH)   // 1723
#define RSPAN   45                        // rows per 4-phase group
#define RTAB    48                        // padded row count in tap table
#define WPITCH  26                        // smem window pitch (floats)
#define ROWS_H  264                       // staged rows per half-frame
#define RLO_STEP 214                      // row offset for half h

// ---------------- scratch (static device globals; no allocs) ----------------
__device__ float g_cosP [NB * TT];        // heterodyne table, planar [band][n]
__device__ float g_xlp  [TT * 24];        // cascade output [n][seq]
__device__ float g_tapS4[RTAB * 160];     // shifted taps [r][p], p grouped by 4
__device__ int   g_i0q  [40];             // i0 of phase 4q

struct BQParams {
    float b0[4], b2[4], a1[4], a2[4];
    float lb0, lb1, lb2, la1, la2;
    float cosco[4];                       // f32(2*pi) * f32(center)
};

// FMA-only cos of large f32 arg (validated R7): CW reduce + sin-half Taylor-9.
__device__ __forceinline__ float cos_poly(float a) {
    const double TWO_PI_D = 6.283185307179586476925287;
    const float  P1 = (float)TWO_PI_D;
    const float  P2 = (float)(TWO_PI_D - (double)((float)TWO_PI_D));
    const float  INV2PI = (float)(1.0 / TWO_PI_D);
    float k = rintf(__fmul_rn(a, INV2PI));
    float r = __fmaf_rn(-k, P1, a);
    r = __fmaf_rn(-k, P2, r);
    float h  = 0.5f * r;
    float h2 = h * h;
    const float c3 = -1.6666667e-1f, c5 = 8.3333333e-3f,
                c7 = -1.9841270e-4f, c9 = 2.7557319e-6f;
    float p = __fmaf_rn(c9, h2, c7);
    p = __fmaf_rn(p, h2, c5);
    p = __fmaf_rn(p, h2, c3);
    p = __fmaf_rn(p, h2, 1.0f);
    float s = p * h;
    return __fmaf_rn(-2.0f * s, s, 1.0f);
}

// ---------------- taps helpers ----------------
__device__ __forceinline__ double tap_tr(int p, int i) {
    const double base = 160.0 * 0.99;
    return (-(double)p / 160.0 + ((double)i - 17.0) / 441.0) * base;
}
__device__ __forceinline__ int tap_i0(int p) {
    const double base = 160.0 * 0.99;
    double lim = 17.0 + 441.0 * ((double)p / 160.0 - 6.0 / base);
    int i0 = (int)ceil(lim);
    if (i0 < 0) i0 = 0;
    while (!(tap_tr(p, i0) > -6.0)) i0++;
    while (i0 > 0 && tap_tr(p, i0 - 1) > -6.0) i0--;
    return i0;
}

// ---------------- merged: taps (blocks 0..29) + cos table (blocks 30..) ----------------
__global__ __launch_bounds__(256) void prep_taps_kernel(BQParams P) {
    int b = blockIdx.x;
    if (b < 30) {
        int gid = b * 256 + threadIdx.x;      // 0..7679 = RTAB*160
        int r = gid / 160, p = gid % 160;
        const double PI_D  = 3.14159265358979323846264338328;
        const double base  = 160.0 * 0.99;
        const double scale = base / 441.0;

        int i0p = tap_i0(p);
        int i0b = tap_i0(p & ~3);
        if (r == 0 && (p & 3) == 0) g_i0q[p >> 2] = i0b;

        int i = i0b + r;
        int d = i - i0p;
        float v = 0.0f;
        if (d >= 0 && d < DTAP && i < 475) {
            double tq = -(double)p / 160.0 + ((double)i - 17.0) / 441.0;
            double tc = tq * base;
            if (tc < -6.0) tc = -6.0;
            if (tc >  6.0) tc =  6.0;
            double w  = cos(tc * PI_D / 6.0 / 2.0);
            w = w * w;
            double tp_ = tc * PI_D;
            double s = (tp_ == 0.0) ? 1.0 : sin(tp_) / tp_;
            v = (float)(s * w * scale);
        }
        g_tapS4[r * 160 + p] = v;
        return;
    }
    int n = (b - 30) * 256 + threadIdx.x;
    if (n >= TT) return;
    const float RINV = 1.0f / 44100.0f;
    float t = __fmul_rn(__int2float_rn(n), RINV);   // XLA recip-multiply (R4)
    g_cosP[0 * TT + n] = cos_poly(__fmul_rn(P.cosco[0], t));
    g_cosP[1 * TT + n] = cos_poly(__fmul_rn(P.cosco[1], t));
    g_cosP[2 * TT + n] = cos_poly(__fmul_rn(P.cosco[2], t));
}

// ---------------- cascade: bandpass -> clip -> mix -> lowpass -> clip ----------------
// Warm-up 128: worst pole 0.9355 -> leakage ~2e-4 (10x under threshold).
__global__ __launch_bounds__(128) void biquad_kernel(const float* __restrict__ x, BQParams P) {
    int w    = (blockIdx.x * blockDim.x + threadIdx.x) >> 5;
    int lane = threadIdx.x & 31;
    if (w >= NCHUNK) return;

    int band  = (lane < 24) ? (lane >> 3) : 0;
    int batch = lane & 7;
    float b0 = P.b0[band], b2 = P.b2[band], a1 = P.a1[band], a2 = P.a2[band];
    float lb0 = P.lb0, lb1 = P.lb1, lb2 = P.lb2, la1 = P.la1, la2 = P.la2;

    int nstart = w * LCH;
    int nend   = min(nstart + LCH, TT);
    int n0     = max(nstart - WCH, 0);
    const float* xr = x + batch * TT;
    const float* cp = g_cosP + band * TT;

    float x1 = 0.f, x2 = 0.f, y1 = 0.f, y2 = 0.f;
    float u1 = 0.f, u2 = 0.f, v1 = 0.f, v2 = 0.f;

#define BQ_STEP(XV, CV, DO_STORE, NIDX)                                       \
    {                                                                          \
        float y  = b0 * (XV) + b2 * x2 - a1 * y1 - a2 * y2;                    \
        x2 = x1; x1 = (XV); y2 = y1; y1 = y;                                   \
        float yc  = fminf(1.0f, fmaxf(-1.0f, y));                              \
        float mix = yc * (CV);                                                 \
        float v   = lb0 * mix + lb1 * u1 + lb2 * u2 - la1 * v1 - la2 * v2;     \
        u2 = u1; u1 = mix; v2 = v1; v1 = v;                                    \
        if (DO_STORE && lane < 24)                                             \
            g_xlp[(NIDX) * 24 + lane] = fminf(1.0f, fmaxf(-1.0f, v));          \
    }

    #pragma unroll 2
    for (int n = n0; n < nstart; n += 4) {
        float4 xv = *reinterpret_cast<const float4*>(&xr[n]);
        float4 cv = *reinterpret_cast<const float4*>(&cp[n]);
        BQ_STEP(xv.x, cv.x, 0, n)
        BQ_STEP(xv.y, cv.y, 0, n)
        BQ_STEP(xv.z, cv.z, 0, n)
        BQ_STEP(xv.w, cv.w, 0, n)
    }
    #pragma unroll 2
    for (int n = nstart; n < nend; n += 4) {
        float4 xv = *reinterpret_cast<const float4*>(&xr[n]);
        float4 cv = *reinterpret_cast<const float4*>(&cp[n]);
        BQ_STEP(xv.x, cv.x, 1, n + 0)
        BQ_STEP(xv.y, cv.y, 1, n + 1)
        BQ_STEP(xv.z, cv.z, 1, n + 2)
        BQ_STEP(xv.w, cv.w, 1, n + 3)
    }
#undef BQ_STEP
}

// packed f32x2 fma: two independent rn FMAs (bit-identical to scalar)
__device__ __forceinline__ void fma2(float2& acc, unsigned long long tap2, const float2& w) {
    unsigned long long a = *reinterpret_cast<unsigned long long*>(&acc);
    unsigned long long wv = *reinterpret_cast<const unsigned long long*>(&w);
    asm("fma.rn.f32x2 %0, %1, %2, %0;" : "+l"(a) : "l"(tap2), "l"(wv));
    acc = *reinterpret_cast<float2*>(&a);
}
__device__ __forceinline__ unsigned long long pack2(float t) {
    unsigned long long r;
    asm("mov.b64 %0, {%1, %1};" : "=l"(r) : "r"(__float_as_uint(t)));
    return r;
}

// ---------------- polyphase resample 44100 -> 16000, half-frame blocks ----------------
// Block (m, h): h selects phase groups q in [20h, 20h+20); those only touch
// window rows [214h, 214h+264) (verified vs i0 with margin). 27.4 KB smem +
// <=64 regs -> 8 blocks/SM.
__global__ __launch_bounds__(128, 8) void resample_kernel(float* __restrict__ out) {
    __shared__ float win[ROWS_H * WPITCH];     // 27.4 KB
    int m   = blockIdx.x;
    int h   = blockIdx.y;                      // 0..1
    int tid = threadIdx.x;
    int rlo = h * RLO_STEP;
    int nbase = 441 * m - 16 + rlo;            // local row r <-> sample nbase + r

    for (int idx = tid; idx < ROWS_H * 12; idx += 128) {
        int r = idx / 12, c2 = idx % 12;
        int n = nbase + r;
        float2 v = make_float2(0.f, 0.f);
        if (n >= 0 && n < TT)
            v = *reinterpret_cast<const float2*>(&g_xlp[n * 24 + c2 * 2]);
        *reinterpret_cast<float2*>(&win[r * WPITCH + c2 * 2]) = v;
    }
    __syncthreads();

    if (tid >= 60) return;
    int sg = tid / 20;                         // 0..2
    int q  = h * 20 + tid % 20;                // phase group
    int rb = g_i0q[q] - 1 - rlo;               // local base window row

    float2 acc[4][4];
    #pragma unroll
    for (int j = 0; j < 4; j++)
        #pragma unroll
        for (int k2 = 0; k2 < 4; k2++) acc[j][k2] = make_float2(0.f, 0.f);

    const float* wrow = &win[rb * WPITCH + sg * 8];
    const float4* tap = reinterpret_cast<const float4*>(&g_tapS4[4 * q]);

    #pragma unroll 3
    for (int r = 0; r < RSPAN; r++) {
        float4 t4 = __ldg(&tap[r * 40]);
        unsigned long long t0 = pack2(t4.x), t1 = pack2(t4.y),
                           t2 = pack2(t4.z), t3 = pack2(t4.w);
        const float* wr = wrow + r * WPITCH;
        float2 w0 = *reinterpret_cast<const float2*>(wr + 0);
        float2 w1 = *reinterpret_cast<const float2*>(wr + 2);
        float2 w2 = *reinterpret_cast<const float2*>(wr + 4);
        float2 w3 = *reinterpret_cast<const float2*>(wr + 6);
        fma2(acc[0][0], t0, w0); fma2(acc[0][1], t0, w1);
        fma2(acc[0][2], t0, w2); fma2(acc[0][3], t0, w3);
        fma2(acc[1][0], t1, w0); fma2(acc[1][1], t1, w1);
        fma2(acc[1][2], t1, w2); fma2(acc[1][3], t1, w3);
        fma2(acc[2][0], t2, w0); fma2(acc[2][1], t2, w1);
        fma2(acc[2][2], t2, w2); fma2(acc[2][3], t2, w3);
        fma2(acc[3][0], t3, w0); fma2(acc[3][1], t3, w1);
        fma2(acc[3][2], t3, w2); fma2(acc[3][3], t3, w3);
    }

    int obase = m * 160 + 4 * q;
    #pragma unroll
    for (int k = 0; k < 8; k++) {
        float4 o;
        o.x = (k & 1) ? acc[0][k >> 1].y : acc[0][k >> 1].x;
        o.y = (k & 1) ? acc[1][k >> 1].y : acc[1][k >> 1].x;
        o.z = (k & 1) ? acc[2][k >> 1].y : acc[2][k >> 1].x;
        o.w = (k & 1) ? acc[3][k >> 1].y : acc[3][k >> 1].x;
        *reinterpret_cast<float4*>(&out[(k * NB + sg) * TOUT + obase]) = o;
    }
}

// ---------------- host ----------------
extern "C" void kernel_launch(void* const* d_in, const int* in_sizes, int n_in,
                              void* d_out, int out_size) {
    (void)in_sizes; (void)n_in; (void)out_size;
    const float* x = (const float*)d_in[0];
    float* out = (float*)d_out;

    const double PI_D = 3.14159265358979323846264338328;
    BQParams P;
    double centers[3] = {4000.0, 12000.0, 19025.0};
    double bws[3]     = {8000.0, 8000.0, 6050.0};
    for (int bnd = 0; bnd < 3; bnd++) {
        double c = centers[bnd];
        double Q = c / bws[bnd]; if (Q < 0.5) Q = 0.5;
        double w0 = 2.0 * PI_D * c / 44100.0;
        double alpha = sin(w0) / (2.0 * Q);
        double a0 = 1.0 + alpha;
        P.b0[bnd] = (float)(alpha / a0);
        P.b2[bnd] = (float)(-alpha / a0);
        P.a1[bnd] = (float)(-2.0 * cos(w0) / a0);
        P.a2[bnd] = (float)((1.0 - alpha) / a0);
        P.cosco[bnd] = (float)(2.0 * PI_D) * (float)c;
    }
    P.b0[3] = P.b2[3] = P.a1[3] = P.a2[3] = 0.0f;
    P.cosco[3] = 0.0f;
    {
        double cutoff = 0.45 * 16000.0;
        double Qc = 0.7071067811865476;
        double w0 = 2.0 * PI_D * cutoff / 44100.0;
        double alpha = sin(w0) / (2.0 * Qc);
        double cc = cos(w0);
        double a0 = 1.0 + alpha;
        P.lb0 = (float)((1.0 - cc) / 2.0 / a0);
        P.lb1 = (float)((1.0 - cc) / a0);
        P.lb2 = (float)((1.0 - cc) / 2.0 / a0);
        P.la1 = (float)(-2.0 * cc / a0);
        P.la2 = (float)((1.0 - alpha) / a0);
    }

    prep_taps_kernel<<<30 + (TT + 255) / 256, 256>>>(P);
    biquad_kernel<<<(NCHUNK * 32 + 127) / 128, 128>>>(x, P);
    dim3 rg(FRAMES, 2);
    resample_kernel<<<rg, 128>>>(out);
}

// round 9
// speedup vs baseline: 10.4490x; 1.0684x over previous
#include <cuda_runtime.h>
#include <math.h>

#define TT      441000
#define NB      3
#define TOUT    160000
#define FRAMES  1000
#define DTAP    36
#define LCH     256
#define WCH     128
#define NCHUNK  ((TT + LCH - 1) / LCH)   // 1723
#define RSPAN   45                        // rows per 4-phase group
#define RTAB    48                        // padded row count in tap table
#define WPITCH  26                        // smem window pitch (floats)
#define ROWS_H  264                       // staged rows per half-frame
#define RLO_STEP 214                      // row offset for half h

// ---------------- scratch (static device globals; no allocs) ----------------
__device__ float g_cosP [NB * TT];        // heterodyne table, planar [band][n]
__device__ float g_xlpP [24 * TT];        // cascade output, planar [seq][n]
__device__ float g_tapS4[RTAB * 160];     // shifted taps [r][p], p grouped by 4
__device__ int   g_i0q  [40];             // i0 of phase 4q

struct BQParams {
    float b0[4], b2[4], a1[4], a2[4];
    float lb0, lb1, lb2, la1, la2;
    float cosco[4];                       // f32(2*pi) * f32(center)
};

// FMA-only cos of large f32 arg (validated R7): CW reduce + sin-half Taylor-9.
__device__ __forceinline__ float cos_poly(float a) {
    const double TWO_PI_D = 6.283185307179586476925287;
    const float  P1 = (float)TWO_PI_D;
    const float  P2 = (float)(TWO_PI_D - (double)((float)TWO_PI_D));
    const float  INV2PI = (float)(1.0 / TWO_PI_D);
    float k = rintf(__fmul_rn(a, INV2PI));
    float r = __fmaf_rn(-k, P1, a);
    r = __fmaf_rn(-k, P2, r);
    float h  = 0.5f * r;
    float h2 = h * h;
    const float c3 = -1.6666667e-1f, c5 = 8.3333333e-3f,
                c7 = -1.9841270e-4f, c9 = 2.7557319e-6f;
    float p = __fmaf_rn(c9, h2, c7);
    p = __fmaf_rn(p, h2, c5);
    p = __fmaf_rn(p, h2, c3);
    p = __fmaf_rn(p, h2, 1.0f);
    float s = p * h;
    return __fmaf_rn(-2.0f * s, s, 1.0f);
}

// ---------------- taps helpers (division-free f64 boundary; values in f32) --------
__device__ __forceinline__ double tap_tr(int p, int i) {
    const double base = 160.0 * 0.99;
    const double INV160 = 1.0 / 160.0, INV441 = 1.0 / 441.0;
    return (-(double)p * INV160 + ((double)i - 17.0) * INV441) * base;
}
__device__ __forceinline__ int tap_i0(int p) {
    const double base = 160.0 * 0.99;
    double lim = 17.0 + 441.0 * ((double)p * (1.0 / 160.0) - 6.0 / base);
    int i0 = (int)ceil(lim);
    if (i0 < 0) i0 = 0;
    while (!(tap_tr(p, i0) > -6.0)) i0++;
    while (i0 > 0 && tap_tr(p, i0 - 1) > -6.0) i0--;
    return i0;
}

// ---------------- merged: taps (blocks 0..29) + cos table (blocks 30..) ----------
__global__ __launch_bounds__(256) void prep_taps_kernel(BQParams P) {
    int b = blockIdx.x;
    if (b < 30) {
        int gid = b * 256 + threadIdx.x;      // 0..7679 = RTAB*160
        int r = gid / 160, p = gid % 160;

        int i0p = tap_i0(p);
        int i0b = tap_i0(p & ~3);
        if (r == 0 && (p & 3) == 0) g_i0q[p >> 2] = i0b;

        int i = i0b + r;
        int d = i - i0p;
        float v = 0.0f;
        if (d >= 0 && d < DTAP && i < 475) {
            const float basef  = 158.4f;
            const float scalef = 158.4f / 441.0f;
            const float PI_F   = 3.14159265358979f;
            float tq = __fmaf_rn((float)p, -(1.0f / 160.0f),
                                 ((float)i - 17.0f) * (1.0f / 441.0f));
            float tc = tq * basef;
            tc = fminf(6.0f, fmaxf(-6.0f, tc));
            float wdw = cospif(tc * (1.0f / 12.0f));
            wdw = wdw * wdw;
            float sp  = sinpif(tc);
            float s   = (tc == 0.0f) ? 1.0f : sp / (tc * PI_F);
            v = s * wdw * scalef;
        }
        g_tapS4[r * 160 + p] = v;
        return;
    }
    int n = (b - 30) * 256 + threadIdx.x;
    if (n >= TT) return;
    const float RINV = 1.0f / 44100.0f;
    float t = __fmul_rn(__int2float_rn(n), RINV);   // XLA recip-multiply (R4)
    g_cosP[0 * TT + n] = cos_poly(__fmul_rn(P.cosco[0], t));
    g_cosP[1 * TT + n] = cos_poly(__fmul_rn(P.cosco[1], t));
    g_cosP[2 * TT + n] = cos_poly(__fmul_rn(P.cosco[2], t));
}

// ---------------- cascade: bandpass -> clip -> mix -> lowpass -> clip ----------------
// Planar output: lane accumulates 4 samples, one float4 STG per group.
__global__ __launch_bounds__(128) void biquad_kernel(const float* __restrict__ x, BQParams P) {
    int w    = (blockIdx.x * blockDim.x + threadIdx.x) >> 5;
    int lane = threadIdx.x & 31;
    if (w >= NCHUNK) return;

    int band  = (lane < 24) ? (lane >> 3) : 0;
    int batch = lane & 7;
    float b0 = P.b0[band], b2 = P.b2[band], a1 = P.a1[band], a2 = P.a2[band];
    float lb0 = P.lb0, lb1 = P.lb1, lb2 = P.lb2, la1 = P.la1, la2 = P.la2;

    int nstart = w * LCH;
    int nend   = min(nstart + LCH, TT);          // multiple of 4
    int n0     = max(nstart - WCH, 0);
    const float* xr = x + batch * TT;
    const float* cp = g_cosP + band * TT;
    float* op = g_xlpP + lane * TT;              // planar row for this seq

    float x1 = 0.f, x2 = 0.f, y1 = 0.f, y2 = 0.f;
    float u1 = 0.f, u2 = 0.f, v1 = 0.f, v2 = 0.f;

#define BQ_CORE(XV, CV, OUT)                                                  \
    {                                                                          \
        float y  = b0 * (XV) + b2 * x2 - a1 * y1 - a2 * y2;                    \
        x2 = x1; x1 = (XV); y2 = y1; y1 = y;                                   \
        float yc  = fminf(1.0f, fmaxf(-1.0f, y));                              \
        float mix = yc * (CV);                                                 \
        float v   = lb0 * mix + lb1 * u1 + lb2 * u2 - la1 * v1 - la2 * v2;     \
        u2 = u1; u1 = mix; v2 = v1; v1 = v;                                    \
        OUT = fminf(1.0f, fmaxf(-1.0f, v));                                    \
    }

    float sink;
    #pragma unroll 2
    for (int n = n0; n < nstart; n += 4) {
        float4 xv = *reinterpret_cast<const float4*>(&xr[n]);
        float4 cv = *reinterpret_cast<const float4*>(&cp[n]);
        BQ_CORE(xv.x, cv.x, sink)
        BQ_CORE(xv.y, cv.y, sink)
        BQ_CORE(xv.z, cv.z, sink)
        BQ_CORE(xv.w, cv.w, sink)
    }
    (void)sink;
    #pragma unroll 2
    for (int n = nstart; n < nend; n += 4) {
        float4 xv = *reinterpret_cast<const float4*>(&xr[n]);
        float4 cv = *reinterpret_cast<const float4*>(&cp[n]);
        float4 ov;
        BQ_CORE(xv.x, cv.x, ov.x)
        BQ_CORE(xv.y, cv.y, ov.y)
        BQ_CORE(xv.z, cv.z, ov.z)
        BQ_CORE(xv.w, cv.w, ov.w)
        if (lane < 24) *reinterpret_cast<float4*>(&op[n]) = ov;
    }
#undef BQ_CORE
}

// packed f32x2 fma: two independent rn FMAs (bit-identical to scalar)
__device__ __forceinline__ void fma2(float2& acc, unsigned long long tap2, const float2& w) {
    unsigned long long a = *reinterpret_cast<unsigned long long*>(&acc);
    unsigned long long wv = *reinterpret_cast<const unsigned long long*>(&w);
    asm("fma.rn.f32x2 %0, %1, %2, %0;" : "+l"(a) : "l"(tap2), "l"(wv));
    acc = *reinterpret_cast<float2*>(&a);
}
__device__ __forceinline__ unsigned long long pack2(float t) {
    unsigned long long r;
    asm("mov.b64 %0, {%1, %1};" : "=l"(r) : "r"(__float_as_uint(t)));
    return r;
}

// ---------------- polyphase resample 44100 -> 16000, half-frame blocks ----------------
__global__ __launch_bounds__(128, 8) void resample_kernel(float* __restrict__ out) {
    __shared__ float win[ROWS_H * WPITCH];     // 27.4 KB
    int m   = blockIdx.x;
    int h   = blockIdx.y;                      // 0..1
    int tid = threadIdx.x;
    int rlo = h * RLO_STEP;
    int nbase = 441 * m - 16 + rlo;            // local row r <-> sample nbase + r

    // stage planar rows: idx = c*ROWS_H + r -> coalesced in r
    for (int idx = tid; idx < 24 * ROWS_H; idx += 128) {
        int c = idx / ROWS_H, r = idx - c * ROWS_H;
        int n = nbase + r;
        float v = 0.0f;
        if (n >= 0 && n < TT) v = g_xlpP[c * TT + n];
        win[r * WPITCH + c] = v;
    }
    __syncthreads();

    if (tid >= 60) return;
    int sg = tid / 20;                         // 0..2
    int q  = h * 20 + tid % 20;                // phase group
    int rb = g_i0q[q] - 1 - rlo;               // local base window row

    float2 acc[4][4];
    #pragma unroll
    for (int j = 0; j < 4; j++)
        #pragma unroll
        for (int k2 = 0; k2 < 4; k2++) acc[j][k2] = make_float2(0.f, 0.f);

    const float* wrow = &win[rb * WPITCH + sg * 8];
    const float4* tap = reinterpret_cast<const float4*>(&g_tapS4[4 * q]);

    #pragma unroll 3
    for (int r = 0; r < RSPAN; r++) {
        float4 t4 = __ldg(&tap[r * 40]);
        unsigned long long t0 = pack2(t4.x), t1 = pack2(t4.y),
                           t2 = pack2(t4.z), t3 = pack2(t4.w);
        const float* wr = wrow + r * WPITCH;
        float2 w0 = *reinterpret_cast<const float2*>(wr + 0);
        float2 w1 = *reinterpret_cast<const float2*>(wr + 2);
        float2 w2 = *reinterpret_cast<const float2*>(wr + 4);
        float2 w3 = *reinterpret_cast<const float2*>(wr + 6);
        fma2(acc[0][0], t0, w0); fma2(acc[0][1], t0, w1);
        fma2(acc[0][2], t0, w2); fma2(acc[0][3], t0, w3);
        fma2(acc[1][0], t1, w0); fma2(acc[1][1], t1, w1);
        fma2(acc[1][2], t1, w2); fma2(acc[1][3], t1, w3);
        fma2(acc[2][0], t2, w0); fma2(acc[2][1], t2, w1);
        fma2(acc[2][2], t2, w2); fma2(acc[2][3], t2, w3);
        fma2(acc[3][0], t3, w0); fma2(acc[3][1], t3, w1);
        fma2(acc[3][2], t3, w2); fma2(acc[3][3], t3, w3);
    }

    int obase = m * 160 + 4 * q;
    #pragma unroll
    for (int k = 0; k < 8; k++) {
        float4 o;
        o.x = (k & 1) ? acc[0][k >> 1].y : acc[0][k >> 1].x;
        o.y = (k & 1) ? acc[1][k >> 1].y : acc[1][k >> 1].x;
        o.z = (k & 1) ? acc[2][k >> 1].y : acc[2][k >> 1].x;
        o.w = (k & 1) ? acc[3][k >> 1].y : acc[3][k >> 1].x;
        *reinterpret_cast<float4*>(&out[(k * NB + sg) * TOUT + obase]) = o;
    }
}

// ---------------- host ----------------
extern "C" void kernel_launch(void* const* d_in, const int* in_sizes, int n_in,
                              void* d_out, int out_size) {
    (void)in_sizes; (void)n_in; (void)out_size;
    const float* x = (const float*)d_in[0];
    float* out = (float*)d_out;

    const double PI_D = 3.14159265358979323846264338328;
    BQParams P;
    double centers[3] = {4000.0, 12000.0, 19025.0};
    double bws[3]     = {8000.0, 8000.0, 6050.0};
    for (int bnd = 0; bnd < 3; bnd++) {
        double c = centers[bnd];
        double Q = c / bws[bnd]; if (Q < 0.5) Q = 0.5;
        double w0 = 2.0 * PI_D * c / 44100.0;
        double alpha = sin(w0) / (2.0 * Q);
        double a0 = 1.0 + alpha;
        P.b0[bnd] = (float)(alpha / a0);
        P.b2[bnd] = (float)(-alpha / a0);
        P.a1[bnd] = (float)(-2.0 * cos(w0) / a0);
        P.a2[bnd] = (float)((1.0 - alpha) / a0);
        P.cosco[bnd] = (float)(2.0 * PI_D) * (float)c;
    }
    P.b0[3] = P.b2[3] = P.a1[3] = P.a2[3] = 0.0f;
    P.cosco[3] = 0.0f;
    {
        double cutoff = 0.45 * 16000.0;
        double Qc = 0.7071067811865476;
        double w0 = 2.0 * PI_D * cutoff / 44100.0;
        double alpha = sin(w0) / (2.0 * Qc);
        double cc = cos(w0);
        double a0 = 1.0 + alpha;
        P.lb0 = (float)((1.0 - cc) / 2.0 / a0);
        P.lb1 = (float)((1.0 - cc) / a0);
        P.lb2 = (float)((1.0 - cc) / 2.0 / a0);
        P.la1 = (float)(-2.0 * cc / a0);
        P.la2 = (float)((1.0 - alpha) / a0);
    }

    prep_taps_kernel<<<30 + (TT + 255) / 256, 256>>>(P);
    biquad_kernel<<<(NCHUNK * 32 + 127) / 128, 128>>>(x, P);
    dim3 rg(FRAMES, 2);
    resample_kernel<<<rg, 128>>>(out);
}